// round 16
// baseline (speedup 1.0000x reference)
#include <cuda_runtime.h>
#include <cstdint>

#define HD 256
#define KD 512
#define NPAD 200448

// ---- GEMM tiling ----
#define MT 128              // rows per CTA
#define NTW 256             // wbig rows per CTA (one nt quarter)
#define KC 32               // k per chunk
#define NCH 16              // chunks (KD/KC)
#define ASTRIDE 36          // smem row stride (floats), conflict-free quads
#define A_FLOATS (MT * ASTRIDE)          // 4608
#define B_FLOATS (NTW * ASTRIDE)         // 9216
#define STG_FLOATS (A_FLOATS + B_FLOATS) // 13824
#define SBIAS_FLOATS 1024
#define SMEM_FLOATS (SBIAS_FLOATS + 3 * STG_FLOATS)   // 42496
#define SMEM_TOTAL (SMEM_FLOATS * 4)                  // 169984 B
#define CSTRIDE 261         // epilogue C staging stride (floats)

__device__ float g_apack[(size_t)NPAD * KD];   // [tf32(x) | h_sum] per row
__device__ float g_csum[(size_t)NPAD * HD];
__device__ float g_wbig[1024 * KD];            // interleaved (i,o,u,f) rows, tf32

// ---------------- helpers ----------------
__device__ __forceinline__ uint32_t smem_u32(const void* p) {
    uint32_t a;
    asm("{ .reg .u64 t; cvta.to.shared.u64 t, %1; cvt.u32.u64 %0, t; }" : "=r"(a) : "l"(p));
    return a;
}
__device__ __forceinline__ uint32_t f2tf32(float f) {
    uint32_t r; asm("cvt.rna.tf32.f32 %0, %1;" : "=r"(r) : "f"(f)); return r;
}
__device__ __forceinline__ void cp16(uint32_t dst, const void* src) {
    asm volatile("cp.async.cg.shared.global [%0], [%1], 16;" :: "r"(dst), "l"(src));
}
__device__ __forceinline__ float ex2f(float x) {
    float r; asm("ex2.approx.f32 %0, %1;" : "=f"(r) : "f"(x)); return r;
}
__device__ __forceinline__ float rcpf(float x) {
    float r; asm("rcp.approx.f32 %0, %1;" : "=f"(r) : "f"(x)); return r;
}
#define L2E 1.4426950408889634f
__device__ __forceinline__ float sigm(float x)  { return rcpf(1.f + ex2f(-x * L2E)); }
__device__ __forceinline__ float tanhx(float x) { return fmaf(2.f, rcpf(1.f + ex2f(-2.f * L2E * x)), -1.f); }

__device__ __forceinline__ void hmma_tf32(float* d, const uint32_t* a, const uint32_t* b) {
    asm volatile(
        "mma.sync.aligned.m16n8k8.row.col.f32.tf32.tf32.f32 "
        "{%0,%1,%2,%3}, {%4,%5,%6,%7}, {%8,%9}, {%0,%1,%2,%3};"
        : "+f"(d[0]), "+f"(d[1]), "+f"(d[2]), "+f"(d[3])
        : "r"(a[0]), "r"(a[1]), "r"(a[2]), "r"(a[3]), "r"(b[0]), "r"(b[1]));
}

// ---------------- kernel 1: pack tf32(x), zero h_sum & c_sum ----------------
__global__ void k_zero(const float* __restrict__ x, int N) {
    int i = blockIdx.x * 256 + threadIdx.x;
    if (i >= N * 64) return;
    int n = i >> 6, q = i & 63;
    float4 xv = reinterpret_cast<const float4*>(x)[i];
    float4 r;
    r.x = __uint_as_float(f2tf32(xv.x));
    r.y = __uint_as_float(f2tf32(xv.y));
    r.z = __uint_as_float(f2tf32(xv.z));
    r.w = __uint_as_float(f2tf32(xv.w));
    float4 z = make_float4(0.f, 0.f, 0.f, 0.f);
    reinterpret_cast<float4*>(g_apack + (size_t)n * KD)[q] = r;
    reinterpret_cast<float4*>(g_apack + (size_t)n * KD + HD)[q] = z;
    reinterpret_cast<float4*>(g_csum)[i] = z;
}

// ---------------- kernel 2: interleaved packed weights (rows 4j+g) ----------------
__global__ void k_wbig(const float* __restrict__ Wiou, const float* __restrict__ Uiou,
                       const float* __restrict__ Ufw) {
    int idx = blockIdx.x * 256 + threadIdx.x;     // 0 .. 1024*512-1
    int r = idx >> 9, k = idx & 511;
    int j = r >> 2, g = r & 3;
    float v;
    if (g == 3) v = (k < HD) ? 0.f : Ufw[j * HD + (k - HD)];
    else        v = (k < HD) ? Wiou[(g * HD + j) * HD + k]
                             : Uiou[(g * HD + j) * HD + (k - HD)];
    g_wbig[idx] = __uint_as_float(f2tf32(v));
}

// ---------------- kernel 3: edge scatter (segment sum) ----------------
__global__ void k_scatter(const float* __restrict__ h, const float* __restrict__ c,
                          const int* __restrict__ src, const int* __restrict__ dst, int E) {
    int i = blockIdx.x * 256 + threadIdx.x;
    if (i >= E * 64) return;
    int e = i >> 6, q = i & 63;
    int s = __ldg(src + e), d = __ldg(dst + e);
    float4 hv = reinterpret_cast<const float4*>(h + (size_t)s * HD)[q];
    float4 cv = reinterpret_cast<const float4*>(c + (size_t)s * HD)[q];
    float* hp = g_apack + (size_t)d * KD + HD + q * 4;
    float* cp = g_csum + (size_t)d * HD + q * 4;
    asm volatile("red.global.add.v4.f32 [%0], {%1,%2,%3,%4};"
                 :: "l"(hp), "f"(hv.x), "f"(hv.y), "f"(hv.z), "f"(hv.w) : "memory");
    asm volatile("red.global.add.v4.f32 [%0], {%1,%2,%3,%4};"
                 :: "l"(cp), "f"(cv.x), "f"(cv.y), "f"(cv.z), "f"(cv.w) : "memory");
}

// ---------------- kernel 4: rna-tf32 round h_sum in place ----------------
__global__ void k_round(int N) {
    int i = blockIdx.x * 256 + threadIdx.x;
    if (i >= N * 64) return;
    int n = i >> 6, q = i & 63;
    float4* p = reinterpret_cast<float4*>(g_apack + (size_t)n * KD + HD) + q;
    float4 v = *p;
    v.x = __uint_as_float(f2tf32(v.x));
    v.y = __uint_as_float(f2tf32(v.y));
    v.z = __uint_as_float(f2tf32(v.z));
    v.w = __uint_as_float(f2tf32(v.w));
    *p = v;
}

// ---------------- kernel 5: mma.sync tf32 GEMM + fused TreeLSTM epilogue ----------------
// CTA: 128 rows x 256 wbig-rows (nt = blockIdx.y quarter). 8 warps = 2(M) x 4(N) of 64x64.
__global__ void __launch_bounds__(256, 1) k_gemm(
    const float* __restrict__ b_iou, const float* __restrict__ U_f_b,
    float* __restrict__ out, int N)
{
    extern __shared__ float sm[];
    const int tid = threadIdx.x, wid = tid >> 5, lane = tid & 31;
    const int m0 = blockIdx.x * MT;
    const int nt = blockIdx.y;
    const int wm = wid >> 2, wn = wid & 3;
    const int r4 = lane >> 2, q = lane & 3;

    // bias staging: sbias[4j+g] interleaved (i,o,u,f)
    sm[4 * tid + 0] = b_iou[tid];
    sm[4 * tid + 1] = b_iou[256 + tid];
    sm[4 * tid + 2] = b_iou[512 + tid];
    sm[4 * tid + 3] = U_f_b[tid];

    const uint32_t sbase = smem_u32(sm);
    const float* __restrict__ Ag = g_apack + (size_t)m0 * KD;
    const float* __restrict__ Bg = g_wbig + (size_t)(nt * NTW) * KD;

    float c[4][8][4];
    #pragma unroll
    for (int mt = 0; mt < 4; ++mt)
        #pragma unroll
        for (int j = 0; j < 8; ++j)
            #pragma unroll
            for (int u = 0; u < 4; ++u) c[mt][j][u] = 0.f;

    // producer: 3072 x 16B per chunk, 12 per thread
    auto issue = [&](int ch) {
        int st = ch % 3;
        uint32_t sa = sbase + (uint32_t)(SBIAS_FLOATS + st * STG_FLOATS) * 4;
        uint32_t sb = sa + A_FLOATS * 4;
        int kc = ch * KC;
        #pragma unroll
        for (int i = 0; i < 12; ++i) {
            int flat = i * 256 + tid;
            if (flat < 1024) {
                int row = flat >> 3, seg = flat & 7;
                cp16(sa + (uint32_t)(row * ASTRIDE + seg * 4) * 4,
                     Ag + (size_t)row * KD + kc + seg * 4);
            } else {
                int f = flat - 1024;
                int row = f >> 3, seg = f & 7;
                cp16(sb + (uint32_t)(row * ASTRIDE + seg * 4) * 4,
                     Bg + (size_t)row * KD + kc + seg * 4);
            }
        }
        asm volatile("cp.async.commit_group;" ::: "memory");
    };

    issue(0); issue(1);
    for (int ch = 0; ch < NCH; ++ch) {
        if (ch + 2 < NCH) issue(ch + 2);
        if (ch <= NCH - 3)      asm volatile("cp.async.wait_group 2;" ::: "memory");
        else if (ch == NCH - 2) asm volatile("cp.async.wait_group 1;" ::: "memory");
        else                    asm volatile("cp.async.wait_group 0;" ::: "memory");
        __syncthreads();

        const float* As = sm + SBIAS_FLOATS + (ch % 3) * STG_FLOATS;
        const float* Bs = As + A_FLOATS;
        const float* apb = As + (wm * 64 + r4) * ASTRIDE + q;
        const float* bpb = Bs + (wn * 64 + r4) * ASTRIDE + q;

        #pragma unroll
        for (int s = 0; s < 4; ++s) {      // 4 k8 steps per chunk
            const int k8 = s * 8;
            uint32_t a[4][4], b[8][2];
            #pragma unroll
            for (int mt = 0; mt < 4; ++mt) {
                const float* ap = apb + mt * 16 * ASTRIDE + k8;
                a[mt][0] = __float_as_uint(ap[0]);
                a[mt][1] = __float_as_uint(ap[8 * ASTRIDE]);
                a[mt][2] = __float_as_uint(ap[4]);
                a[mt][3] = __float_as_uint(ap[8 * ASTRIDE + 4]);
            }
            #pragma unroll
            for (int j = 0; j < 8; ++j) {
                const float* bp = bpb + j * 8 * ASTRIDE + k8;
                b[j][0] = __float_as_uint(bp[0]);
                b[j][1] = __float_as_uint(bp[4]);
            }
            #pragma unroll
            for (int mt = 0; mt < 4; ++mt)
                #pragma unroll
                for (int j = 0; j < 8; ++j)
                    hmma_tf32(c[mt][j], a[mt], b[j]);
        }
        __syncthreads();
    }

    // ---- stage C to smem (stride CSTRIDE, conflict-free re-read) ----
    float* Cs = sm + SBIAS_FLOATS;
    #pragma unroll
    for (int mt = 0; mt < 4; ++mt) {
        #pragma unroll
        for (int j = 0; j < 8; ++j) {
            int row0 = wm * 64 + mt * 16 + r4;
            int col = wn * 64 + j * 8 + 2 * q;
            Cs[row0 * CSTRIDE + col]           = c[mt][j][0];
            Cs[row0 * CSTRIDE + col + 1]       = c[mt][j][1];
            Cs[(row0 + 8) * CSTRIDE + col]     = c[mt][j][2];
            Cs[(row0 + 8) * CSTRIDE + col + 1] = c[mt][j][3];
        }
    }
    __syncthreads();

    // ---- fused TreeLSTM epilogue: thread -> (row = tid&127, half = tid>>7) ----
    const int row = tid & 127, half = tid >> 7;
    const int m = m0 + row;
    if (m < N) {
        const float* crow = Cs + row * CSTRIDE + half * 128;
        const float* bb = sm + nt * 256 + half * 128;
        const float* cs = g_csum + (size_t)m * HD + nt * 64 + half * 32;
        float* ho = out + (size_t)m * HD + nt * 64 + half * 32;
        float* co = out + (size_t)N * HD + (size_t)m * HD + nt * 64 + half * 32;
        #pragma unroll
        for (int jj = 0; jj < 8; ++jj) {   // 8 x float4 outputs (32 gate-groups)
            float4 cv = *reinterpret_cast<const float4*>(cs + jj * 4);
            float csv[4] = {cv.x, cv.y, cv.z, cv.w};
            float hn[4], cn[4];
            #pragma unroll
            for (int u = 0; u < 4; ++u) {
                int base = jj * 16 + u * 4;
                float pi = crow[base + 0] + bb[base + 0];
                float po = crow[base + 1] + bb[base + 1];
                float pu = crow[base + 2] + bb[base + 2];
                float pf = crow[base + 3] + bb[base + 3];
                float cnew = fmaf(sigm(pi), tanhx(pu), sigm(pf) * csv[u]);
                cn[u] = cnew;
                hn[u] = sigm(po) * tanhx(cnew);
            }
            *reinterpret_cast<float4*>(ho + jj * 4) = make_float4(hn[0], hn[1], hn[2], hn[3]);
            *reinterpret_cast<float4*>(co + jj * 4) = make_float4(cn[0], cn[1], cn[2], cn[3]);
        }
    }
}

// ---------------- launch ----------------
extern "C" void kernel_launch(void* const* d_in, const int* in_sizes, int n_in,
                              void* d_out, int out_size)
{
    const float* x    = (const float*)d_in[0];
    const float* h    = (const float*)d_in[1];
    const float* c    = (const float*)d_in[2];
    const int*   src  = (const int*)d_in[3];
    const int*   dst  = (const int*)d_in[4];
    const float* Wiou = (const float*)d_in[5];
    const float* Uiou = (const float*)d_in[6];
    const float* biou = (const float*)d_in[7];
    const float* Ufw  = (const float*)d_in[8];
    const float* Ufb  = (const float*)d_in[9];
    int N = in_sizes[0] / HD;
    int E = in_sizes[3];

    cudaFuncSetAttribute(k_gemm, cudaFuncAttributeMaxDynamicSharedMemorySize, SMEM_TOTAL);

    k_zero<<<(N * 64 + 255) / 256, 256>>>(x, N);
    k_wbig<<<(1024 * 512) / 256, 256>>>(Wiou, Uiou, Ufw);
    k_scatter<<<(E * 64 + 255) / 256, 256>>>(h, c, src, dst, E);
    k_round<<<(N * 64 + 255) / 256, 256>>>(N);
    dim3 grid((N + MT - 1) / MT, 4);
    k_gemm<<<grid, 256, SMEM_TOTAL>>>(biou, Ufb, (float*)d_out, N);
}